// round 7
// baseline (speedup 1.0000x reference)
#include <cuda_runtime.h>
#include <cuda_bf16.h>
#include <math.h>
#include <stdint.h>

// Problem constants (inputs/targets: 8192 x 2048 fp32)
#define NROWS 8192
#define NCOLS 2048
#define LAMB  0.1

#define CLN  4      // CTAs per cluster
#define WPC  2048   // elements per CTA window
#define THR  512    // threads per CTA
#define E    4      // elements per thread (in registers)

// Scratch: per-row squared error
__device__ float g_err[NROWS];

// ---------------------------------------------------------------------------
// Kernel 1: err[row] = sum_d (x[row,d]-t[row,d])^2
// 2 rows per block, 8 front-batched LDG.128 per thread (MLP_p1 = 8).
// ---------------------------------------------------------------------------
__global__ __launch_bounds__(256) void row_sqerr_kernel(
    const float4* __restrict__ x, const float4* __restrict__ t)
{
    const int r0 = blockIdx.x * 2;
    const float4* x0 = x + (size_t)r0 * (NCOLS / 4);
    const float4* t0 = t + (size_t)r0 * (NCOLS / 4);
    const int c0 = threadIdx.x;
    const int c1 = threadIdx.x + 256;

    // front-batched loads: row r0 (a0,a1 / b0,b1), row r0+1 (a2,a3 / b2,b3)
    float4 a0 = __ldcg(&x0[c0]);
    float4 a1 = __ldcg(&x0[c1]);
    float4 a2 = __ldcg(&x0[512 + c0]);
    float4 a3 = __ldcg(&x0[512 + c1]);
    float4 b0 = __ldcg(&t0[c0]);
    float4 b1 = __ldcg(&t0[c1]);
    float4 b2 = __ldcg(&t0[512 + c0]);
    float4 b3 = __ldcg(&t0[512 + c1]);

    float d;
    float acc0 = 0.0f, acc1 = 0.0f;
    d = a0.x - b0.x; acc0 += d * d;  d = a0.y - b0.y; acc0 += d * d;
    d = a0.z - b0.z; acc0 += d * d;  d = a0.w - b0.w; acc0 += d * d;
    d = a1.x - b1.x; acc0 += d * d;  d = a1.y - b1.y; acc0 += d * d;
    d = a1.z - b1.z; acc0 += d * d;  d = a1.w - b1.w; acc0 += d * d;
    d = a2.x - b2.x; acc1 += d * d;  d = a2.y - b2.y; acc1 += d * d;
    d = a2.z - b2.z; acc1 += d * d;  d = a2.w - b2.w; acc1 += d * d;
    d = a3.x - b3.x; acc1 += d * d;  d = a3.y - b3.y; acc1 += d * d;
    d = a3.z - b3.z; acc1 += d * d;  d = a3.w - b3.w; acc1 += d * d;

    // two independent warp reductions
    #pragma unroll
    for (int off = 16; off > 0; off >>= 1) {
        acc0 += __shfl_down_sync(0xFFFFFFFFu, acc0, off);
        acc1 += __shfl_down_sync(0xFFFFFFFFu, acc1, off);
    }

    __shared__ float ws0[8], ws1[8];
    int lane = threadIdx.x & 31;
    int wid  = threadIdx.x >> 5;
    if (lane == 0) { ws0[wid] = acc0; ws1[wid] = acc1; }
    __syncthreads();

    if (wid == 0) {
        float v0 = (lane < 8) ? ws0[lane] : 0.0f;
        float v1 = (lane < 8) ? ws1[lane] : 0.0f;
        #pragma unroll
        for (int off = 4; off > 0; off >>= 1) {
            v0 += __shfl_down_sync(0xFFFFFFFFu, v0, off);
            v1 += __shfl_down_sync(0xFFFFFFFFu, v1, off);
        }
        if (lane == 0) { g_err[r0] = v0; g_err[r0 + 1] = v1; }
    }
}

// ---------------------------------------------------------------------------
// Cluster / DSMEM helpers
// ---------------------------------------------------------------------------
__device__ __forceinline__ uint32_t smem_u32(const void* p)
{
    uint32_t a;
    asm("{ .reg .u64 t; cvta.to.shared.u64 t, %1; cvt.u32.u64 %0, t; }"
        : "=r"(a) : "l"(p));
    return a;
}
__device__ __forceinline__ uint32_t my_ctarank()
{
    uint32_t r;
    asm("mov.u32 %0, %%cluster_ctarank;" : "=r"(r));
    return r;
}
__device__ __forceinline__ uint32_t mapa_u32(uint32_t a, uint32_t rank)
{
    uint32_t r;
    asm("mapa.shared::cluster.u32 %0, %1, %2;" : "=r"(r) : "r"(a), "r"(rank));
    return r;
}
__device__ __forceinline__ float4 ld_dsm_f4(uint32_t a)
{
    float4 v;
    asm volatile("ld.shared::cluster.v4.f32 {%0,%1,%2,%3}, [%4];"
                 : "=f"(v.x), "=f"(v.y), "=f"(v.z), "=f"(v.w) : "r"(a));
    return v;
}
__device__ __forceinline__ double ld_dsm_f64(uint32_t a)
{
    unsigned long long u;
    asm volatile("ld.shared::cluster.b64 %0, [%1];" : "=l"(u) : "r"(a));
    return __longlong_as_double((long long)u);
}
__device__ __forceinline__ uint32_t ld_dsm_b32(uint32_t a)
{
    uint32_t u;
    asm volatile("ld.shared::cluster.b32 %0, [%1];" : "=r"(u) : "r"(a));
    return u;
}
#define CLUSTER_SYNC() do { \
    asm volatile("barrier.cluster.arrive.aligned;" ::: "memory"); \
    asm volatile("barrier.cluster.wait.aligned;"   ::: "memory"); \
} while (0)

// ---------------------------------------------------------------------------
// Bitonic helpers (E = 4 elems/thread)
// ---------------------------------------------------------------------------
__device__ __forceinline__ void cmpswap(float& a, float& b, bool up)
{
    float lo = fminf(a, b);
    float hi = fmaxf(a, b);
    a = up ? lo : hi;
    b = up ? hi : lo;
}

__device__ __forceinline__ void combine4(float v[E], float4 p, bool keep_min)
{
    v[0] = keep_min ? fminf(v[0], p.x) : fmaxf(v[0], p.x);
    v[1] = keep_min ? fminf(v[1], p.y) : fmaxf(v[1], p.y);
    v[2] = keep_min ? fminf(v[2], p.z) : fmaxf(v[2], p.z);
    v[3] = keep_min ? fminf(v[3], p.w) : fmaxf(v[3], p.w);
}

__device__ __forceinline__ void shfl_stage4(float v[E], int d, bool keep_min)
{
    #pragma unroll
    for (int e = 0; e < E; e++) {
        float p = __shfl_xor_sync(0xFFFFFFFFu, v[e], d);
        v[e] = keep_min ? fminf(v[e], p) : fmaxf(v[e], p);
    }
}

// In-CTA smem substage (128 <= j <= 1024). One float4/thread: s4[t] = v[0..3].
__device__ __forceinline__ void smem_stage(float v[E], float4* s4, int t, int j, bool upT)
{
    s4[t] = make_float4(v[0], v[1], v[2], v[3]);
    __syncthreads();
    int dj = j >> 2;
    float4 p = s4[t ^ dj];
    combine4(v, p, (upT == ((t & dj) == 0)));
    __syncthreads();
}

// Cross-CTA substage (j >= WPC): read partner CTA's window via DSMEM.
__device__ __forceinline__ void dsmem_stage(float v[E], float4* s4, uint32_t sbase,
                                            int t, uint32_t prank, bool keep_min)
{
    s4[t] = make_float4(v[0], v[1], v[2], v[3]);
    __syncthreads();
    CLUSTER_SYNC();                               // all windows written
    uint32_t pa = mapa_u32(sbase, prank);
    float4 p = ld_dsm_f4(pa + (uint32_t)t * 16u);
    combine4(v, p, keep_min);
    CLUSTER_SYNC();                               // all reads done before reuse
}

// ---------------------------------------------------------------------------
// Kernel 2: cluster of 4 CTAs x 512 threads; each CTA owns 2048 elements
// (4/thread in registers). Full bitonic sort + fused finalize.
// ---------------------------------------------------------------------------
__global__ __launch_bounds__(THR) __cluster_dims__(CLN, 1, 1)
void sort_finalize_cluster(float* __restrict__ out)
{
    __shared__ float  s[WPC];                 // 8 KB window
    __shared__ double s_w1[16], s_w2[16];
    __shared__ double s_tot[2];               // this CTA's (sum, sumsq)
    __shared__ double s_ct1[CLN], s_ct2[CLN]; // gathered CTA totals
    __shared__ float  s_bh[16];
    __shared__ int    s_bk[16];
    __shared__ double s_bp[16];
    __shared__ float  s_cbh;                  // CTA-best (exported via DSMEM)
    __shared__ int    s_cbk;
    __shared__ double s_cbp;

    const int t = threadIdx.x;
    const uint32_t rank = my_ctarank();
    const int gi = (int)rank * WPC + E * t;   // global index of first owned elem
    const int N = NROWS;
    float4* s4 = reinterpret_cast<float4*>(s);
    const uint32_t sbase = smem_u32(s);

    // load 4 consecutive elements
    float v[E];
    {
        const float4* g4 = reinterpret_cast<const float4*>(g_err);
        float4 a = g4[rank * (WPC / 4) + t];
        v[0] = a.x; v[1] = a.y; v[2] = a.z; v[3] = a.w;
    }

    // ---- k = 2 : dirs (up, down) within thread ----
    cmpswap(v[0], v[1], true);
    cmpswap(v[2], v[3], false);

    // ---- k = 4 : whole thread-quad one direction ----
    {
        const bool up4 = ((gi & 4) == 0);
        cmpswap(v[0], v[2], up4);
        cmpswap(v[1], v[3], up4);
        cmpswap(v[0], v[1], up4);
        cmpswap(v[2], v[3], up4);
    }

    // ---- k = 8 .. 8192 ----
    for (int k = 8; k <= 8192; k <<= 1) {
        const bool upT = ((gi & k) == 0);

        // cross-CTA substages: j = k/2 .. 2048  (k >= 4096 only; 3 total)
        for (int j = k >> 1; j >= 2048; j >>= 1)
            dsmem_stage(v, s4, sbase, t, rank ^ (uint32_t)(j >> 11),
                        (upT == ((gi & j) == 0)));

        // smem substages: j = min(k/2, 1024) .. 128
        int jsm = (k >> 1) < 1024 ? (k >> 1) : 1024;
        for (int j = jsm; j >= 128; j >>= 1)
            smem_stage(v, s4, t, j, upT);

        // shfl substages: j = min(k/2, 64) .. 4   (lane xor d = j/4 <= 16)
        int jsh = (k >> 1) < 64 ? (k >> 1) : 64;
        for (int j = jsh; j >= 4; j >>= 1) {
            int d = j >> 2;
            shfl_stage4(v, d, (upT == ((t & d) == 0)));
        }

        // intra substages: j = 2, 1 (uniform direction)
        cmpswap(v[0], v[2], upT);
        cmpswap(v[1], v[3], upT);
        cmpswap(v[0], v[1], upT);
        cmpswap(v[2], v[3], upT);
    }

    // ---- Finalize: v[0..3] = sorted elements [gi, gi+4) ascending ----
    const int lane = t & 31;
    const int wid  = t >> 5;

    double l1 = 0.0, l2 = 0.0;
    #pragma unroll
    for (int i = 0; i < E; i++) {
        double d = (double)v[i];
        l1 += d;
        l2 += d * d;
    }

    // warp inclusive scan of (l1, l2)
    double i1 = l1, i2 = l2;
    #pragma unroll
    for (int off = 1; off < 32; off <<= 1) {
        double a = __shfl_up_sync(0xFFFFFFFFu, i1, off);
        double b = __shfl_up_sync(0xFFFFFFFFu, i2, off);
        if (lane >= off) { i1 += a; i2 += b; }
    }
    if (lane == 31) { s_w1[wid] = i1; s_w2[wid] = i2; }
    __syncthreads();

    if (wid == 0) {
        double a1 = (lane < 16) ? s_w1[lane] : 0.0;
        double a2 = (lane < 16) ? s_w2[lane] : 0.0;
        #pragma unroll
        for (int off = 1; off < 16; off <<= 1) {
            double x = __shfl_up_sync(0xFFFFFFFFu, a1, off);
            double y = __shfl_up_sync(0xFFFFFFFFu, a2, off);
            if (lane >= off) { a1 += x; a2 += y; }
        }
        if (lane < 16) { s_w1[lane] = a1; s_w2[lane] = a2; }
    }
    __syncthreads();

    // Export this CTA's totals, gather all 4 CTAs' totals via DSMEM.
    if (t == 0) { s_tot[0] = s_w1[15]; s_tot[1] = s_w2[15]; }
    __syncthreads();
    CLUSTER_SYNC();
    if (t < CLN) {
        uint32_t pa = mapa_u32(smem_u32(s_tot), (uint32_t)t);
        s_ct1[t] = ld_dsm_f64(pa);
        s_ct2[t] = ld_dsm_f64(pa + 8u);
    }
    __syncthreads();

    double tot1 = 0.0, tot2 = 0.0, cb1 = 0.0, cb2 = 0.0;
    #pragma unroll
    for (int r = 0; r < CLN; r++) {
        tot1 += s_ct1[r];
        tot2 += s_ct2[r];
        if (r < (int)rank) { cb1 += s_ct1[r]; cb2 += s_ct2[r]; }
    }

    double wbase1 = (wid == 0) ? 0.0 : s_w1[wid - 1];
    double wbase2 = (wid == 0) ? 0.0 : s_w2[wid - 1];
    double p1 = cb1 + wbase1 + i1 - l1;   // exclusive prefix before this chunk
    double p2 = cb2 + wbase2 + i2 - l2;

    const double ts = tot2 - tot1 * tot1 / (double)N;
    const float invTS = (float)(1.0 / ts);

    float  bestH = INFINITY;
    int    bestK = 0x7FFFFFFF;
    double bestP1 = 0.0;
    #pragma unroll
    for (int i = 0; i < E; i++) {
        double d = (double)v[i];
        p1 += d;
        p2 += d * d;
        int k = gi + i + 1;
        if (k <= N - 1) {
            double cin  = (double)k;
            double cout = (double)(N - k);
            double r1   = tot1 - p1;
            double num_in  = p2 * cin - p1 * p1;            // within_in  * cin
            double num_out = (tot2 - p2) * cout - r1 * r1;  // within_out * cout
            float h = ((float)num_in  / (float)cin +
                       (float)num_out / (float)cout) * invTS;
            if (h < bestH) { bestH = h; bestK = k; bestP1 = p1; }
        }
    }

    // warp argmin (h, then k for first-index tiebreak)
    #pragma unroll
    for (int off = 16; off > 0; off >>= 1) {
        float  h2 = __shfl_down_sync(0xFFFFFFFFu, bestH, off);
        int    k2 = __shfl_down_sync(0xFFFFFFFFu, bestK, off);
        double q2 = __shfl_down_sync(0xFFFFFFFFu, bestP1, off);
        if (h2 < bestH || (h2 == bestH && k2 < bestK)) {
            bestH = h2; bestK = k2; bestP1 = q2;
        }
    }
    if (lane == 0) { s_bh[wid] = bestH; s_bk[wid] = bestK; s_bp[wid] = bestP1; }
    __syncthreads();

    if (t == 0) {
        float  h = s_bh[0];
        int    k = s_bk[0];
        double q = s_bp[0];
        #pragma unroll
        for (int w = 1; w < 16; w++)
            if (s_bh[w] < h || (s_bh[w] == h && s_bk[w] < k)) {
                h = s_bh[w]; k = s_bk[w]; q = s_bp[w];
            }
        s_cbh = h; s_cbk = k; s_cbp = q;
    }
    __syncthreads();
    CLUSTER_SYNC();                                   // all CTA-bests exported

    if (rank == 0 && t == 0) {
        float  h = INFINITY;
        int    k = 0x7FFFFFFF;
        double q = 0.0;
        uint32_t ah = smem_u32(&s_cbh);
        uint32_t ak = smem_u32(&s_cbk);
        uint32_t ap = smem_u32(&s_cbp);
        #pragma unroll
        for (int r = 0; r < CLN; r++) {
            float  h2 = __uint_as_float(ld_dsm_b32(mapa_u32(ah, (uint32_t)r)));
            int    k2 = (int)ld_dsm_b32(mapa_u32(ak, (uint32_t)r));
            double q2 = ld_dsm_f64(mapa_u32(ap, (uint32_t)r));
            if (h2 < h || (h2 == h && k2 < k)) { h = h2; k = k2; q = q2; }
        }
        double obj = q / (double)k;
        out[0] = (float)(obj + LAMB * (double)h);
    }
    CLUSTER_SYNC();   // keep all CTAs resident until rank 0 finished reading
}

// ---------------------------------------------------------------------------
extern "C" void kernel_launch(void* const* d_in, const int* in_sizes, int n_in,
                              void* d_out, int out_size)
{
    const float4* x = (const float4*)d_in[0];
    const float4* t = (const float4*)d_in[1];
    float* out = (float*)d_out;

    row_sqerr_kernel<<<NROWS / 2, 256>>>(x, t);
    sort_finalize_cluster<<<CLN, THR>>>(out);
}

// round 8
// speedup vs baseline: 1.0009x; 1.0009x over previous
#include <cuda_runtime.h>
#include <cuda_bf16.h>
#include <math.h>
#include <stdint.h>

// Problem constants (inputs/targets: 8192 x 2048 fp32)
#define NROWS 8192
#define NCOLS 2048
#define LAMB  0.1

#define CLN  4      // CTAs per cluster
#define WPC  2048   // elements per CTA window
#define THR  256    // threads per CTA
#define E    8      // elements per thread (in registers)

// Scratch: per-row squared error
__device__ float g_err[NROWS];

// ---------------------------------------------------------------------------
// Kernel 1: err[row] = sum_d (x[row,d]-t[row,d])^2
// 4 rows per block, 16 front-batched LDG.128 per thread (MLP_p1 = 16).
// ---------------------------------------------------------------------------
__global__ __launch_bounds__(256) void row_sqerr_kernel(
    const float4* __restrict__ x, const float4* __restrict__ t)
{
    const int r0 = blockIdx.x * 4;
    const float4* xr = x + (size_t)r0 * (NCOLS / 4);
    const float4* tr = t + (size_t)r0 * (NCOLS / 4);
    const int tid = threadIdx.x;

    // front-batched loads: 4 rows x 2 float4 per array
    float4 a[8], b[8];
    #pragma unroll
    for (int r = 0; r < 4; r++) {
        a[r*2+0] = __ldcg(&xr[r * 512 + tid]);
        a[r*2+1] = __ldcg(&xr[r * 512 + 256 + tid]);
    }
    #pragma unroll
    for (int r = 0; r < 4; r++) {
        b[r*2+0] = __ldcg(&tr[r * 512 + tid]);
        b[r*2+1] = __ldcg(&tr[r * 512 + 256 + tid]);
    }

    float acc[4];
    #pragma unroll
    for (int r = 0; r < 4; r++) {
        float s = 0.0f, d;
        #pragma unroll
        for (int h = 0; h < 2; h++) {
            float4 av = a[r*2+h], bv = b[r*2+h];
            d = av.x - bv.x; s += d * d;
            d = av.y - bv.y; s += d * d;
            d = av.z - bv.z; s += d * d;
            d = av.w - bv.w; s += d * d;
        }
        acc[r] = s;
    }

    #pragma unroll
    for (int off = 16; off > 0; off >>= 1)
        #pragma unroll
        for (int r = 0; r < 4; r++)
            acc[r] += __shfl_down_sync(0xFFFFFFFFu, acc[r], off);

    __shared__ float ws[4][8];
    int lane = tid & 31;
    int wid  = tid >> 5;
    if (lane == 0)
        #pragma unroll
        for (int r = 0; r < 4; r++) ws[r][wid] = acc[r];
    __syncthreads();

    if (wid == 0) {
        #pragma unroll
        for (int r = 0; r < 4; r++) {
            float v = (lane < 8) ? ws[r][lane] : 0.0f;
            #pragma unroll
            for (int off = 4; off > 0; off >>= 1)
                v += __shfl_down_sync(0xFFFFFFFFu, v, off);
            if (lane == 0) g_err[r0 + r] = v;
        }
    }
}

// ---------------------------------------------------------------------------
// Cluster / DSMEM helpers
// ---------------------------------------------------------------------------
__device__ __forceinline__ uint32_t smem_u32(const void* p)
{
    uint32_t a;
    asm("{ .reg .u64 t; cvta.to.shared.u64 t, %1; cvt.u32.u64 %0, t; }"
        : "=r"(a) : "l"(p));
    return a;
}
__device__ __forceinline__ uint32_t my_ctarank()
{
    uint32_t r;
    asm("mov.u32 %0, %%cluster_ctarank;" : "=r"(r));
    return r;
}
__device__ __forceinline__ uint32_t mapa_u32(uint32_t a, uint32_t rank)
{
    uint32_t r;
    asm("mapa.shared::cluster.u32 %0, %1, %2;" : "=r"(r) : "r"(a), "r"(rank));
    return r;
}
__device__ __forceinline__ float4 ld_dsm_f4(uint32_t a)
{
    float4 v;
    asm volatile("ld.shared::cluster.v4.f32 {%0,%1,%2,%3}, [%4];"
                 : "=f"(v.x), "=f"(v.y), "=f"(v.z), "=f"(v.w) : "r"(a));
    return v;
}
__device__ __forceinline__ double ld_dsm_f64(uint32_t a)
{
    unsigned long long u;
    asm volatile("ld.shared::cluster.b64 %0, [%1];" : "=l"(u) : "r"(a));
    return __longlong_as_double((long long)u);
}
__device__ __forceinline__ uint32_t ld_dsm_b32(uint32_t a)
{
    uint32_t u;
    asm volatile("ld.shared::cluster.b32 %0, [%1];" : "=r"(u) : "r"(a));
    return u;
}
#define CLUSTER_ARRIVE() asm volatile("barrier.cluster.arrive.aligned;" ::: "memory")
#define CLUSTER_WAIT()   asm volatile("barrier.cluster.wait.aligned;"   ::: "memory")
#define CLUSTER_SYNC() do { CLUSTER_ARRIVE(); CLUSTER_WAIT(); } while (0)

// ---------------------------------------------------------------------------
// Bitonic helpers (E = 8 elems/thread)
// ---------------------------------------------------------------------------
__device__ __forceinline__ void cmpswap(float& a, float& b, bool up)
{
    float lo = fminf(a, b);
    float hi = fmaxf(a, b);
    a = up ? lo : hi;
    b = up ? hi : lo;
}

template<int J>
__device__ __forceinline__ void intra8(float v[E], int kmask, bool uniform, bool upT)
{
    #pragma unroll
    for (int e = 0; e < E; e++)
        if ((e & J) == 0) {
            bool up = uniform ? upT : ((e & kmask) == 0);
            cmpswap(v[e], v[e | J], up);
        }
}

__device__ __forceinline__ void combine8(float v[E], float4 p0, float4 p1, bool keep_min)
{
    float p[E] = {p0.x, p0.y, p0.z, p0.w, p1.x, p1.y, p1.z, p1.w};
    #pragma unroll
    for (int e = 0; e < E; e++)
        v[e] = keep_min ? fminf(v[e], p[e]) : fmaxf(v[e], p[e]);
}

__device__ __forceinline__ void shfl_stage8(float v[E], int d, bool keep_min)
{
    #pragma unroll
    for (int e = 0; e < E; e++) {
        float p = __shfl_xor_sync(0xFFFFFFFFu, v[e], d);
        v[e] = keep_min ? fminf(v[e], p) : fmaxf(v[e], p);
    }
}

// In-CTA smem substage, SINGLE barrier (caller alternates buffers).
// Layout: s4[t] = v[0..3], s4[256+t] = v[4..7]; partner thread = t ^ (j/8).
__device__ __forceinline__ void smem_stage1(float v[E], float4* s4, int t, int j, bool upT)
{
    s4[t]       = make_float4(v[0], v[1], v[2], v[3]);
    s4[256 + t] = make_float4(v[4], v[5], v[6], v[7]);
    __syncthreads();
    int pt = t ^ (j >> 3);
    float4 p0 = s4[pt];
    float4 p1 = s4[256 + pt];
    combine8(v, p0, p1, (upT == ((t & (j >> 3)) == 0)));
}

// Cross-CTA substage, SINGLE cluster barrier (caller alternates buffers).
__device__ __forceinline__ void dsmem_stage1(float v[E], float4* s4, uint32_t sbase,
                                             int t, uint32_t prank, bool keep_min)
{
    s4[t]       = make_float4(v[0], v[1], v[2], v[3]);
    s4[256 + t] = make_float4(v[4], v[5], v[6], v[7]);
    CLUSTER_ARRIVE();          // every thread arrives after its own stores
    CLUSTER_WAIT();            // all CTAs' windows written
    uint32_t pa = mapa_u32(sbase, prank);
    float4 p0 = ld_dsm_f4(pa + (uint32_t)t * 16u);
    float4 p1 = ld_dsm_f4(pa + (uint32_t)(256 + t) * 16u);
    combine8(v, p0, p1, keep_min);
}

// ---------------------------------------------------------------------------
// Kernel 2: cluster of 4 CTAs x 256 threads; each CTA owns 2048 elements
// (8/thread in registers). Full bitonic sort + fused finalize.
// ---------------------------------------------------------------------------
__global__ __launch_bounds__(THR) __cluster_dims__(CLN, 1, 1)
void sort_finalize_cluster(float* __restrict__ out)
{
    __shared__ float4 sA[2][512];             // double-buffered smem windows
    __shared__ float4 sD[2][512];             // double-buffered DSMEM windows
    __shared__ double s_w1[8], s_w2[8];
    __shared__ double s_tot[2];               // this CTA's (sum, sumsq)
    __shared__ double s_ct1[CLN], s_ct2[CLN]; // gathered CTA totals
    __shared__ float  s_bh[8];
    __shared__ int    s_bk[8];
    __shared__ double s_bp[8];
    __shared__ float  s_cbh;                  // CTA-best (exported via DSMEM)
    __shared__ int    s_cbk;
    __shared__ double s_cbp;

    const int t = threadIdx.x;
    const uint32_t rank = my_ctarank();
    const int gi = (int)rank * WPC + E * t;   // global index of first owned elem
    const int N = NROWS;
    const uint32_t sbaseD0 = smem_u32(&sD[0][0]);
    const uint32_t sbaseD1 = smem_u32(&sD[1][0]);
    int pA = 0, pD = 0;

    // load 8 consecutive elements
    float v[E];
    {
        const float4* g4 = reinterpret_cast<const float4*>(g_err);
        #pragma unroll
        for (int q = 0; q < 2; q++) {
            float4 a = g4[rank * (WPC / 4) + 2 * t + q];
            v[4*q+0] = a.x; v[4*q+1] = a.y; v[4*q+2] = a.z; v[4*q+3] = a.w;
        }
    }

    // ---- k = 2, 4, 8 : fully intra-thread (per-element direction) ----
    intra8<1>(v, 2, false, false);

    intra8<2>(v, 4, false, false);
    intra8<1>(v, 4, false, false);

    intra8<4>(v, 8, false, false);
    intra8<2>(v, 8, false, false);
    intra8<1>(v, 8, false, false);

    // ---- k = 16 .. 2048 : local to this CTA ----
    for (int k = 16; k <= 2048; k <<= 1) {
        const bool upT = ((gi & k) == 0);

        for (int j = k >> 1; j >= 256; j >>= 1) {      // smem (k>=512 only)
            smem_stage1(v, sA[pA], t, j, upT);
            pA ^= 1;
        }

        int js = (k >> 1) < 128 ? (k >> 1) : 128;
        for (int j = js; j >= 8; j >>= 1) {            // shfl (d = j/8 <= 16)
            int d = j >> 3;
            shfl_stage8(v, d, (upT == ((t & d) == 0)));
        }

        intra8<4>(v, k, true, upT);
        intra8<2>(v, k, true, upT);
        intra8<1>(v, k, true, upT);
    }

    // ---- k = 4096 : one cross-CTA substage (j=2048), rest local ----
    {
        const bool upT = ((gi & 4096) == 0);
        dsmem_stage1(v, sD[pD], pD ? sbaseD1 : sbaseD0, t, rank ^ 1u,
                     (upT == ((gi & 2048) == 0)));
        pD ^= 1;
        for (int j = 1024; j >= 256; j >>= 1) { smem_stage1(v, sA[pA], t, j, upT); pA ^= 1; }
        for (int j = 128; j >= 8; j >>= 1) {
            int d = j >> 3;
            shfl_stage8(v, d, (upT == ((t & d) == 0)));
        }
        intra8<4>(v, 4096, true, upT);
        intra8<2>(v, 4096, true, upT);
        intra8<1>(v, 4096, true, upT);
    }

    // ---- k = 8192 : two cross-CTA substages (j=4096, 2048), rest local ----
    {
        const bool upT = true;   // (gi & 8192) == 0 for all
        dsmem_stage1(v, sD[pD], pD ? sbaseD1 : sbaseD0, t, rank ^ 2u,
                     ((gi & 4096) == 0));
        pD ^= 1;
        dsmem_stage1(v, sD[pD], pD ? sbaseD1 : sbaseD0, t, rank ^ 1u,
                     ((gi & 2048) == 0));
        pD ^= 1;
        for (int j = 1024; j >= 256; j >>= 1) { smem_stage1(v, sA[pA], t, j, upT); pA ^= 1; }
        for (int j = 128; j >= 8; j >>= 1) {
            int d = j >> 3;
            shfl_stage8(v, d, (upT == ((t & d) == 0)));
        }
        intra8<4>(v, 8192, true, upT);
        intra8<2>(v, 8192, true, upT);
        intra8<1>(v, 8192, true, upT);
    }

    // ---- Finalize: v[0..7] = sorted elements [gi, gi+8) ascending ----
    const int lane = t & 31;
    const int wid  = t >> 5;

    double l1 = 0.0, l2 = 0.0;
    #pragma unroll
    for (int i = 0; i < E; i++) {
        double d = (double)v[i];
        l1 += d;
        l2 += d * d;
    }

    // warp inclusive scan of (l1, l2)
    double i1 = l1, i2 = l2;
    #pragma unroll
    for (int off = 1; off < 32; off <<= 1) {
        double a = __shfl_up_sync(0xFFFFFFFFu, i1, off);
        double b = __shfl_up_sync(0xFFFFFFFFu, i2, off);
        if (lane >= off) { i1 += a; i2 += b; }
    }
    if (lane == 31) { s_w1[wid] = i1; s_w2[wid] = i2; }
    __syncthreads();

    if (wid == 0) {
        double a1 = (lane < 8) ? s_w1[lane] : 0.0;
        double a2 = (lane < 8) ? s_w2[lane] : 0.0;
        #pragma unroll
        for (int off = 1; off < 8; off <<= 1) {
            double x = __shfl_up_sync(0xFFFFFFFFu, a1, off);
            double y = __shfl_up_sync(0xFFFFFFFFu, a2, off);
            if (lane >= off) { a1 += x; a2 += y; }
        }
        if (lane < 8) { s_w1[lane] = a1; s_w2[lane] = a2; }
    }
    __syncthreads();

    // Export this CTA's totals, gather all 4 CTAs' totals via DSMEM.
    if (t == 0) { s_tot[0] = s_w1[7]; s_tot[1] = s_w2[7]; }
    __syncthreads();
    CLUSTER_SYNC();
    if (t < CLN) {
        uint32_t pa = mapa_u32(smem_u32(s_tot), (uint32_t)t);
        s_ct1[t] = ld_dsm_f64(pa);
        s_ct2[t] = ld_dsm_f64(pa + 8u);
    }
    __syncthreads();

    double tot1 = 0.0, tot2 = 0.0, cb1 = 0.0, cb2 = 0.0;
    #pragma unroll
    for (int r = 0; r < CLN; r++) {
        tot1 += s_ct1[r];
        tot2 += s_ct2[r];
        if (r < (int)rank) { cb1 += s_ct1[r]; cb2 += s_ct2[r]; }
    }

    double wbase1 = (wid == 0) ? 0.0 : s_w1[wid - 1];
    double wbase2 = (wid == 0) ? 0.0 : s_w2[wid - 1];
    double p1 = cb1 + wbase1 + i1 - l1;   // exclusive prefix before this chunk
    double p2 = cb2 + wbase2 + i2 - l2;

    const double ts = tot2 - tot1 * tot1 / (double)N;
    const float invTS = (float)(1.0 / ts);

    float  bestH = INFINITY;
    int    bestK = 0x7FFFFFFF;
    double bestP1 = 0.0;
    #pragma unroll
    for (int i = 0; i < E; i++) {
        double d = (double)v[i];
        p1 += d;
        p2 += d * d;
        int k = gi + i + 1;
        if (k <= N - 1) {
            double cin  = (double)k;
            double cout = (double)(N - k);
            double r1   = tot1 - p1;
            double num_in  = p2 * cin - p1 * p1;            // within_in  * cin
            double num_out = (tot2 - p2) * cout - r1 * r1;  // within_out * cout
            float h = ((float)num_in  / (float)cin +
                       (float)num_out / (float)cout) * invTS;
            if (h < bestH) { bestH = h; bestK = k; bestP1 = p1; }
        }
    }

    // warp argmin (h, then k for first-index tiebreak)
    #pragma unroll
    for (int off = 16; off > 0; off >>= 1) {
        float  h2 = __shfl_down_sync(0xFFFFFFFFu, bestH, off);
        int    k2 = __shfl_down_sync(0xFFFFFFFFu, bestK, off);
        double q2 = __shfl_down_sync(0xFFFFFFFFu, bestP1, off);
        if (h2 < bestH || (h2 == bestH && k2 < bestK)) {
            bestH = h2; bestK = k2; bestP1 = q2;
        }
    }
    if (lane == 0) { s_bh[wid] = bestH; s_bk[wid] = bestK; s_bp[wid] = bestP1; }
    __syncthreads();

    if (t == 0) {
        float  h = s_bh[0];
        int    k = s_bk[0];
        double q = s_bp[0];
        #pragma unroll
        for (int w = 1; w < 8; w++)
            if (s_bh[w] < h || (s_bh[w] == h && s_bk[w] < k)) {
                h = s_bh[w]; k = s_bk[w]; q = s_bp[w];
            }
        s_cbh = h; s_cbk = k; s_cbp = q;
    }
    __syncthreads();
    CLUSTER_SYNC();                                   // all CTA-bests exported

    if (rank == 0 && t == 0) {
        float  h = INFINITY;
        int    k = 0x7FFFFFFF;
        double q = 0.0;
        uint32_t ah = smem_u32(&s_cbh);
        uint32_t ak = smem_u32(&s_cbk);
        uint32_t ap = smem_u32(&s_cbp);
        #pragma unroll
        for (int r = 0; r < CLN; r++) {
            float  h2 = __uint_as_float(ld_dsm_b32(mapa_u32(ah, (uint32_t)r)));
            int    k2 = (int)ld_dsm_b32(mapa_u32(ak, (uint32_t)r));
            double q2 = ld_dsm_f64(mapa_u32(ap, (uint32_t)r));
            if (h2 < h || (h2 == h && k2 < k)) { h = h2; k = k2; q = q2; }
        }
        double obj = q / (double)k;
        out[0] = (float)(obj + LAMB * (double)h);
    }
    CLUSTER_SYNC();   // keep all CTAs resident until rank 0 finished reading
}

// ---------------------------------------------------------------------------
extern "C" void kernel_launch(void* const* d_in, const int* in_sizes, int n_in,
                              void* d_out, int out_size)
{
    const float4* x = (const float4*)d_in[0];
    const float4* t = (const float4*)d_in[1];
    float* out = (float*)d_out;

    row_sqerr_kernel<<<NROWS / 4, 256>>>(x, t);
    sort_finalize_cluster<<<CLN, THR>>>(out);
}

// round 10
// speedup vs baseline: 1.0597x; 1.0588x over previous
#include <cuda_runtime.h>
#include <cuda_bf16.h>
#include <math.h>
#include <stdint.h>

// Problem constants (inputs/targets: 8192 x 2048 fp32)
#define NROWS 8192
#define NCOLS 2048
#define LAMB  0.1

#define CLN  4      // CTAs per cluster
#define WPC  2048   // elements per CTA window
#define THR  256    // threads per CTA
#define E    8      // elements per thread (in registers)

// Scratch: per-row squared error
__device__ float g_err[NROWS];

// ---------------------------------------------------------------------------
// Kernel 1: err[row] = sum_d (x[row,d]-t[row,d])^2
// 2 rows per block, 8 front-batched LDG.128 per thread (MLP_p1 = 8).
// (Round-7 measured best: ~20.9us composite. 4-row/MLP16 regressed.)
// ---------------------------------------------------------------------------
__global__ __launch_bounds__(256) void row_sqerr_kernel(
    const float4* __restrict__ x, const float4* __restrict__ t)
{
    const int r0 = blockIdx.x * 2;
    const float4* x0 = x + (size_t)r0 * (NCOLS / 4);
    const float4* t0 = t + (size_t)r0 * (NCOLS / 4);
    const int c0 = threadIdx.x;
    const int c1 = threadIdx.x + 256;

    // front-batched loads: row r0 (a0,a1 / b0,b1), row r0+1 (a2,a3 / b2,b3)
    float4 a0 = __ldcg(&x0[c0]);
    float4 a1 = __ldcg(&x0[c1]);
    float4 a2 = __ldcg(&x0[512 + c0]);
    float4 a3 = __ldcg(&x0[512 + c1]);
    float4 b0 = __ldcg(&t0[c0]);
    float4 b1 = __ldcg(&t0[c1]);
    float4 b2 = __ldcg(&t0[512 + c0]);
    float4 b3 = __ldcg(&t0[512 + c1]);

    float d;
    float acc0 = 0.0f, acc1 = 0.0f;
    d = a0.x - b0.x; acc0 += d * d;  d = a0.y - b0.y; acc0 += d * d;
    d = a0.z - b0.z; acc0 += d * d;  d = a0.w - b0.w; acc0 += d * d;
    d = a1.x - b1.x; acc0 += d * d;  d = a1.y - b1.y; acc0 += d * d;
    d = a1.z - b1.z; acc0 += d * d;  d = a1.w - b1.w; acc0 += d * d;
    d = a2.x - b2.x; acc1 += d * d;  d = a2.y - b2.y; acc1 += d * d;
    d = a2.z - b2.z; acc1 += d * d;  d = a2.w - b2.w; acc1 += d * d;
    d = a3.x - b3.x; acc1 += d * d;  d = a3.y - b3.y; acc1 += d * d;
    d = a3.z - b3.z; acc1 += d * d;  d = a3.w - b3.w; acc1 += d * d;

    // two independent warp reductions
    #pragma unroll
    for (int off = 16; off > 0; off >>= 1) {
        acc0 += __shfl_down_sync(0xFFFFFFFFu, acc0, off);
        acc1 += __shfl_down_sync(0xFFFFFFFFu, acc1, off);
    }

    __shared__ float ws0[8], ws1[8];
    int lane = threadIdx.x & 31;
    int wid  = threadIdx.x >> 5;
    if (lane == 0) { ws0[wid] = acc0; ws1[wid] = acc1; }
    __syncthreads();

    if (wid == 0) {
        float v0 = (lane < 8) ? ws0[lane] : 0.0f;
        float v1 = (lane < 8) ? ws1[lane] : 0.0f;
        #pragma unroll
        for (int off = 4; off > 0; off >>= 1) {
            v0 += __shfl_down_sync(0xFFFFFFFFu, v0, off);
            v1 += __shfl_down_sync(0xFFFFFFFFu, v1, off);
        }
        if (lane == 0) { g_err[r0] = v0; g_err[r0 + 1] = v1; }
    }
}

// ---------------------------------------------------------------------------
// Cluster / DSMEM helpers
// ---------------------------------------------------------------------------
__device__ __forceinline__ uint32_t smem_u32(const void* p)
{
    uint32_t a;
    asm("{ .reg .u64 t; cvta.to.shared.u64 t, %1; cvt.u32.u64 %0, t; }"
        : "=r"(a) : "l"(p));
    return a;
}
__device__ __forceinline__ uint32_t my_ctarank()
{
    uint32_t r;
    asm("mov.u32 %0, %%cluster_ctarank;" : "=r"(r));
    return r;
}
__device__ __forceinline__ uint32_t mapa_u32(uint32_t a, uint32_t rank)
{
    uint32_t r;
    asm("mapa.shared::cluster.u32 %0, %1, %2;" : "=r"(r) : "r"(a), "r"(rank));
    return r;
}
__device__ __forceinline__ float4 ld_dsm_f4(uint32_t a)
{
    float4 v;
    asm volatile("ld.shared::cluster.v4.f32 {%0,%1,%2,%3}, [%4];"
                 : "=f"(v.x), "=f"(v.y), "=f"(v.z), "=f"(v.w) : "r"(a));
    return v;
}
__device__ __forceinline__ double ld_dsm_f64(uint32_t a)
{
    unsigned long long u;
    asm volatile("ld.shared::cluster.b64 %0, [%1];" : "=l"(u) : "r"(a));
    return __longlong_as_double((long long)u);
}
__device__ __forceinline__ uint32_t ld_dsm_b32(uint32_t a)
{
    uint32_t u;
    asm volatile("ld.shared::cluster.b32 %0, [%1];" : "=r"(u) : "r"(a));
    return u;
}
#define CLUSTER_ARRIVE() asm volatile("barrier.cluster.arrive.aligned;" ::: "memory")
#define CLUSTER_WAIT()   asm volatile("barrier.cluster.wait.aligned;"   ::: "memory")
#define CLUSTER_SYNC() do { CLUSTER_ARRIVE(); CLUSTER_WAIT(); } while (0)

// ---------------------------------------------------------------------------
// Bitonic helpers (E = 8 elems/thread)
// ---------------------------------------------------------------------------
__device__ __forceinline__ void cmpswap(float& a, float& b, bool up)
{
    float lo = fminf(a, b);
    float hi = fmaxf(a, b);
    a = up ? lo : hi;
    b = up ? hi : lo;
}

template<int J>
__device__ __forceinline__ void intra8(float v[E], int kmask, bool uniform, bool upT)
{
    #pragma unroll
    for (int e = 0; e < E; e++)
        if ((e & J) == 0) {
            bool up = uniform ? upT : ((e & kmask) == 0);
            cmpswap(v[e], v[e | J], up);
        }
}

__device__ __forceinline__ void combine8(float v[E], float4 p0, float4 p1, bool keep_min)
{
    float p[E] = {p0.x, p0.y, p0.z, p0.w, p1.x, p1.y, p1.z, p1.w};
    #pragma unroll
    for (int e = 0; e < E; e++)
        v[e] = keep_min ? fminf(v[e], p[e]) : fmaxf(v[e], p[e]);
}

__device__ __forceinline__ void shfl_stage8(float v[E], int d, bool keep_min)
{
    #pragma unroll
    for (int e = 0; e < E; e++) {
        float p = __shfl_xor_sync(0xFFFFFFFFu, v[e], d);
        v[e] = keep_min ? fminf(v[e], p) : fmaxf(v[e], p);
    }
}

// In-CTA smem substage, SINGLE barrier (caller alternates buffers).
__device__ __forceinline__ void smem_stage1(float v[E], float4* s4, int t, int j, bool upT)
{
    s4[t]       = make_float4(v[0], v[1], v[2], v[3]);
    s4[256 + t] = make_float4(v[4], v[5], v[6], v[7]);
    __syncthreads();
    int pt = t ^ (j >> 3);
    float4 p0 = s4[pt];
    float4 p1 = s4[256 + pt];
    combine8(v, p0, p1, (upT == ((t & (j >> 3)) == 0)));
}

// Cross-CTA substage, SINGLE cluster barrier (caller alternates buffers).
__device__ __forceinline__ void dsmem_stage1(float v[E], float4* s4, uint32_t sbase,
                                             int t, uint32_t prank, bool keep_min)
{
    s4[t]       = make_float4(v[0], v[1], v[2], v[3]);
    s4[256 + t] = make_float4(v[4], v[5], v[6], v[7]);
    CLUSTER_ARRIVE();          // every thread arrives after its own stores
    CLUSTER_WAIT();            // all CTAs' windows written
    uint32_t pa = mapa_u32(sbase, prank);
    float4 p0 = ld_dsm_f4(pa + (uint32_t)t * 16u);
    float4 p1 = ld_dsm_f4(pa + (uint32_t)(256 + t) * 16u);
    combine8(v, p0, p1, keep_min);
}

// ---------------------------------------------------------------------------
// Kernel 2: cluster of 4 CTAs x 256 threads; each CTA owns 2048 elements
// (8/thread in registers). Full bitonic sort + fused finalize.
// ---------------------------------------------------------------------------
__global__ __launch_bounds__(THR) __cluster_dims__(CLN, 1, 1)
void sort_finalize_cluster(float* __restrict__ out)
{
    __shared__ float4 sA[2][512];             // double-buffered smem windows
    __shared__ float4 sD[2][512];             // double-buffered DSMEM windows
    __shared__ double s_w1[8], s_w2[8];
    __shared__ double s_tot[2];               // this CTA's (sum, sumsq)
    __shared__ double s_ct1[CLN], s_ct2[CLN]; // gathered CTA totals
    __shared__ float  s_bh[8];
    __shared__ int    s_bk[8];
    __shared__ double s_bp[8];
    __shared__ float  s_cbh;                  // CTA-best (exported via DSMEM)
    __shared__ int    s_cbk;
    __shared__ double s_cbp;

    const int t = threadIdx.x;
    const uint32_t rank = my_ctarank();
    const int gi = (int)rank * WPC + E * t;   // global index of first owned elem
    const int N = NROWS;
    const uint32_t sbaseD0 = smem_u32(&sD[0][0]);
    const uint32_t sbaseD1 = smem_u32(&sD[1][0]);
    int pA = 0, pD = 0;

    // load 8 consecutive elements
    float v[E];
    {
        const float4* g4 = reinterpret_cast<const float4*>(g_err);
        #pragma unroll
        for (int q = 0; q < 2; q++) {
            float4 a = g4[rank * (WPC / 4) + 2 * t + q];
            v[4*q+0] = a.x; v[4*q+1] = a.y; v[4*q+2] = a.z; v[4*q+3] = a.w;
        }
    }

    // ---- k = 2, 4, 8 : fully intra-thread (per-element direction) ----
    intra8<1>(v, 2, false, false);

    intra8<2>(v, 4, false, false);
    intra8<1>(v, 4, false, false);

    intra8<4>(v, 8, false, false);
    intra8<2>(v, 8, false, false);
    intra8<1>(v, 8, false, false);

    // ---- k = 16 .. 2048 : local to this CTA (fully unrolled) ----
    #pragma unroll
    for (int k = 16; k <= 2048; k <<= 1) {
        const bool upT = ((gi & k) == 0);

        #pragma unroll
        for (int j = k >> 1; j >= 256; j >>= 1) {      // smem (k>=512 only)
            smem_stage1(v, sA[pA], t, j, upT);
            pA ^= 1;
        }

        const int js = (k >> 1) < 128 ? (k >> 1) : 128;
        #pragma unroll
        for (int j = js; j >= 8; j >>= 1) {            // shfl (d = j/8 <= 16)
            int d = j >> 3;
            shfl_stage8(v, d, (upT == ((t & d) == 0)));
        }

        intra8<4>(v, k, true, upT);
        intra8<2>(v, k, true, upT);
        intra8<1>(v, k, true, upT);
    }

    // ---- k = 4096 : one cross-CTA substage (j=2048), rest local ----
    {
        const bool upT = ((gi & 4096) == 0);
        dsmem_stage1(v, sD[pD], pD ? sbaseD1 : sbaseD0, t, rank ^ 1u,
                     (upT == ((gi & 2048) == 0)));
        pD ^= 1;
        #pragma unroll
        for (int j = 1024; j >= 256; j >>= 1) { smem_stage1(v, sA[pA], t, j, upT); pA ^= 1; }
        #pragma unroll
        for (int j = 128; j >= 8; j >>= 1) {
            int d = j >> 3;
            shfl_stage8(v, d, (upT == ((t & d) == 0)));
        }
        intra8<4>(v, 4096, true, upT);
        intra8<2>(v, 4096, true, upT);
        intra8<1>(v, 4096, true, upT);
    }

    // ---- k = 8192 : two cross-CTA substages (j=4096, 2048), rest local ----
    {
        const bool upT = true;   // (gi & 8192) == 0 for all
        dsmem_stage1(v, sD[pD], pD ? sbaseD1 : sbaseD0, t, rank ^ 2u,
                     ((gi & 4096) == 0));
        pD ^= 1;
        dsmem_stage1(v, sD[pD], pD ? sbaseD1 : sbaseD0, t, rank ^ 1u,
                     ((gi & 2048) == 0));
        pD ^= 1;
        #pragma unroll
        for (int j = 1024; j >= 256; j >>= 1) { smem_stage1(v, sA[pA], t, j, upT); pA ^= 1; }
        #pragma unroll
        for (int j = 128; j >= 8; j >>= 1) {
            int d = j >> 3;
            shfl_stage8(v, d, (upT == ((t & d) == 0)));
        }
        intra8<4>(v, 8192, true, upT);
        intra8<2>(v, 8192, true, upT);
        intra8<1>(v, 8192, true, upT);
    }

    // ---- Finalize: v[0..7] = sorted elements [gi, gi+8) ascending ----
    const int lane = t & 31;
    const int wid  = t >> 5;

    double l1 = 0.0, l2 = 0.0;
    #pragma unroll
    for (int i = 0; i < E; i++) {
        double d = (double)v[i];
        l1 += d;
        l2 += d * d;
    }

    // warp inclusive scan of (l1, l2)
    double i1 = l1, i2 = l2;
    #pragma unroll
    for (int off = 1; off < 32; off <<= 1) {
        double a = __shfl_up_sync(0xFFFFFFFFu, i1, off);
        double b = __shfl_up_sync(0xFFFFFFFFu, i2, off);
        if (lane >= off) { i1 += a; i2 += b; }
    }
    if (lane == 31) { s_w1[wid] = i1; s_w2[wid] = i2; }
    __syncthreads();

    if (wid == 0) {
        double a1 = (lane < 8) ? s_w1[lane] : 0.0;
        double a2 = (lane < 8) ? s_w2[lane] : 0.0;
        #pragma unroll
        for (int off = 1; off < 8; off <<= 1) {
            double x = __shfl_up_sync(0xFFFFFFFFu, a1, off);
            double y = __shfl_up_sync(0xFFFFFFFFu, a2, off);
            if (lane >= off) { a1 += x; a2 += y; }
        }
        if (lane < 8) { s_w1[lane] = a1; s_w2[lane] = a2; }
    }
    __syncthreads();

    // Export this CTA's totals, gather all 4 CTAs' totals via DSMEM.
    if (t == 0) { s_tot[0] = s_w1[7]; s_tot[1] = s_w2[7]; }
    __syncthreads();
    CLUSTER_SYNC();
    if (t < CLN) {
        uint32_t pa = mapa_u32(smem_u32(s_tot), (uint32_t)t);
        s_ct1[t] = ld_dsm_f64(pa);
        s_ct2[t] = ld_dsm_f64(pa + 8u);
    }
    __syncthreads();

    double tot1 = 0.0, tot2 = 0.0, cb1 = 0.0, cb2 = 0.0;
    #pragma unroll
    for (int r = 0; r < CLN; r++) {
        tot1 += s_ct1[r];
        tot2 += s_ct2[r];
        if (r < (int)rank) { cb1 += s_ct1[r]; cb2 += s_ct2[r]; }
    }

    double wbase1 = (wid == 0) ? 0.0 : s_w1[wid - 1];
    double wbase2 = (wid == 0) ? 0.0 : s_w2[wid - 1];
    double p1 = cb1 + wbase1 + i1 - l1;   // exclusive prefix before this chunk
    double p2 = cb2 + wbase2 + i2 - l2;

    const double ts = tot2 - tot1 * tot1 / (double)N;
    const float invTS = (float)(1.0 / ts);

    float  bestH = INFINITY;
    int    bestK = 0x7FFFFFFF;
    double bestP1 = 0.0;
    #pragma unroll
    for (int i = 0; i < E; i++) {
        double d = (double)v[i];
        p1 += d;
        p2 += d * d;
        int k = gi + i + 1;
        if (k <= N - 1) {
            double cin  = (double)k;
            double cout = (double)(N - k);
            double r1   = tot1 - p1;
            double num_in  = p2 * cin - p1 * p1;            // within_in  * cin
            double num_out = (tot2 - p2) * cout - r1 * r1;  // within_out * cout
            float h = ((float)num_in  / (float)cin +
                       (float)num_out / (float)cout) * invTS;
            if (h < bestH) { bestH = h; bestK = k; bestP1 = p1; }
        }
    }

    // warp argmin (h, then k for first-index tiebreak)
    #pragma unroll
    for (int off = 16; off > 0; off >>= 1) {
        float  h2 = __shfl_down_sync(0xFFFFFFFFu, bestH, off);
        int    k2 = __shfl_down_sync(0xFFFFFFFFu, bestK, off);
        double q2 = __shfl_down_sync(0xFFFFFFFFu, bestP1, off);
        if (h2 < bestH || (h2 == bestH && k2 < bestK)) {
            bestH = h2; bestK = k2; bestP1 = q2;
        }
    }
    if (lane == 0) { s_bh[wid] = bestH; s_bk[wid] = bestK; s_bp[wid] = bestP1; }
    __syncthreads();

    if (t == 0) {
        float  h = s_bh[0];
        int    k = s_bk[0];
        double q = s_bp[0];
        #pragma unroll
        for (int w = 1; w < 8; w++)
            if (s_bh[w] < h || (s_bh[w] == h && s_bk[w] < k)) {
                h = s_bh[w]; k = s_bk[w]; q = s_bp[w];
            }
        s_cbh = h; s_cbk = k; s_cbp = q;
    }
    __syncthreads();
    CLUSTER_SYNC();                                   // all CTA-bests exported

    if (rank == 0 && t == 0) {
        float  h = INFINITY;
        int    k = 0x7FFFFFFF;
        double q = 0.0;
        uint32_t ah = smem_u32(&s_cbh);
        uint32_t ak = smem_u32(&s_cbk);
        uint32_t ap = smem_u32(&s_cbp);
        #pragma unroll
        for (int r = 0; r < CLN; r++) {
            float  h2 = __uint_as_float(ld_dsm_b32(mapa_u32(ah, (uint32_t)r)));
            int    k2 = (int)ld_dsm_b32(mapa_u32(ak, (uint32_t)r));
            double q2 = ld_dsm_f64(mapa_u32(ap, (uint32_t)r));
            if (h2 < h || (h2 == h && k2 < k)) { h = h2; k = k2; q = q2; }
        }
        double obj = q / (double)k;
        out[0] = (float)(obj + LAMB * (double)h);
    }
    CLUSTER_SYNC();   // keep all CTAs resident until rank 0 finished reading
}

// ---------------------------------------------------------------------------
extern "C" void kernel_launch(void* const* d_in, const int* in_sizes, int n_in,
                              void* d_out, int out_size)
{
    const float4* x = (const float4*)d_in[0];
    const float4* t = (const float4*)d_in[1];
    float* out = (float*)d_out;

    row_sqerr_kernel<<<NROWS / 2, 256>>>(x, t);
    sort_finalize_cluster<<<CLN, THR>>>(out);
}